// round 15
// baseline (speedup 1.0000x reference)
#include <cuda_runtime.h>
#include <math.h>

#define BB 64      // batch
#define TT 512     // seq len
#define FF 128     // input features
#define HH 512     // hidden
#define G4 2048    // 4*H
#define NR 32768   // B*T

// ---------------- scratch (device globals; no allocations) ----------------
__device__ float g_xw[(size_t)NR * G4];        // [t][b][4H]  (256 MB)
__device__ float g_h1[(size_t)TT * HH * BB];   // [t][k][b]   (64 MB)
__device__ float g_h2[(size_t)TT * HH * BB];   // [t][k][b]
__device__ __align__(128) float g_hT[2][HH * BB];  // ping-pong h state, [k][b]
__device__ float g_scale[2 * HH];              // BN folded scale per layer
__device__ float g_shift[2 * HH];              // BN folded shift per layer
__device__ unsigned g_bar[2];                  // grid barrier counters

// ---------------- packed f32x2 helpers (sm_103a dual-FMA path) ----------------
__device__ __forceinline__ unsigned long long pack2(float lo, float hi) {
    unsigned long long r;
    asm("mov.b64 %0, {%1, %2};" : "=l"(r) : "f"(lo), "f"(hi));
    return r;
}
__device__ __forceinline__ unsigned long long ffma2(unsigned long long a,
                                                    unsigned long long b,
                                                    unsigned long long c) {
    unsigned long long d;
    asm("fma.rn.f32x2 %0, %1, %2, %3;" : "=l"(d) : "l"(a), "l"(b), "l"(c));
    return d;
}
__device__ __forceinline__ unsigned long long addf2(unsigned long long a,
                                                    unsigned long long b) {
    unsigned long long d;
    asm("add.rn.f32x2 %0, %1, %2;" : "=l"(d) : "l"(a), "l"(b));
    return d;
}
__device__ __forceinline__ float2 unpack2(unsigned long long v) {
    float2 f;
    asm("mov.b64 {%0, %1}, %2;" : "=f"(f.x), "=f"(f.y) : "l"(v));
    return f;
}
// mbarrier wait (parity), acquire semantics for subsequent LDS reads
__device__ __forceinline__ void mbar_wait(unsigned mbar, unsigned parity) {
    asm volatile(
        "{\n\t"
        ".reg .pred P;\n\t"
        "LAB_WAIT_%=:\n\t"
        "mbarrier.try_wait.parity.acquire.cta.shared::cta.b64 P, [%0], %1, 0x989680;\n\t"
        "@P bra LAB_DONE_%=;\n\t"
        "bra LAB_WAIT_%=;\n\t"
        "LAB_DONE_%=:\n\t"
        "}"
        :: "r"(mbar), "r"(parity) : "memory");
}

// ---------------- zero h state + barrier counters ----------------
__global__ void zero_state() {
    int idx = blockIdx.x * blockDim.x + threadIdx.x;
    if (idx < HH * BB) {
        g_hT[0][idx] = 0.f;
        g_hT[1][idx] = 0.f;
    }
    if (idx < 2) g_bar[idx] = 0u;
}

// ---------------- GEMM core tile: 64m x 128n, 256 threads, 16 f32x2 accs ----------
// Thread (tm = tid>>4, tn = tid&15): rows 4tm..4tm+3, f32x2 cols 4tn..4tn+3
// Per k: 1x LDS.128 A (2 distinct/warp -> broadcast) + 2x LDS.128 B + 16 FFMA2.

// GEMM 1: g_xw[t*64+b][n] = x[b*T+t][:] @ Wx1 + b1
__global__ __launch_bounds__(256) void gemm_xw1(const float* __restrict__ x,
                                                const float* __restrict__ W,
                                                const float* __restrict__ bias) {
    __shared__ __align__(16) float As[16][68];    // [k][m]
    __shared__ __align__(16) float Bs[16][136];   // [k][n] (f32x2-pair natural)
    const int tid = threadIdx.x;
    const int m0 = blockIdx.y * 64;
    const int n0 = blockIdx.x * 128;
    const int tm = tid >> 4;          // 0..15 -> 4 rows
    const int tn = tid & 15;          // 0..15 -> 4 ull cols (8 floats)
    unsigned long long acc[4][4] = {};
    for (int k0 = 0; k0 < FF; k0 += 16) {
        {   // A: 64m x 16k, transpose into As[k][m]
            int m = tid >> 2, q = tid & 3;
            float4 v = *reinterpret_cast<const float4*>(x + (size_t)(m0 + m) * FF + k0 + q * 4);
            As[q * 4 + 0][m] = v.x; As[q * 4 + 1][m] = v.y;
            As[q * 4 + 2][m] = v.z; As[q * 4 + 3][m] = v.w;
        }
        {   // B: 16k x 128n
            int kk = tid >> 4, c = (tid & 15) << 3;
            const float* src = W + (size_t)(k0 + kk) * G4 + n0 + c;
            float4 v0 = *reinterpret_cast<const float4*>(src);
            float4 v1 = *reinterpret_cast<const float4*>(src + 4);
            *reinterpret_cast<float4*>(&Bs[kk][c])     = v0;
            *reinterpret_cast<float4*>(&Bs[kk][c + 4]) = v1;
        }
        __syncthreads();
#pragma unroll
        for (int k = 0; k < 16; k++) {
            float4 a = *reinterpret_cast<const float4*>(&As[k][tm << 2]);
            const unsigned long long* bp =
                reinterpret_cast<const unsigned long long*>(&Bs[k][tn << 3]);
            unsigned long long b0 = bp[0], b1 = bp[1], b2 = bp[2], b3 = bp[3];
            unsigned long long a0 = pack2(a.x, a.x), a1 = pack2(a.y, a.y);
            unsigned long long a2 = pack2(a.z, a.z), a3 = pack2(a.w, a.w);
            acc[0][0] = ffma2(a0, b0, acc[0][0]); acc[0][1] = ffma2(a0, b1, acc[0][1]);
            acc[0][2] = ffma2(a0, b2, acc[0][2]); acc[0][3] = ffma2(a0, b3, acc[0][3]);
            acc[1][0] = ffma2(a1, b0, acc[1][0]); acc[1][1] = ffma2(a1, b1, acc[1][1]);
            acc[1][2] = ffma2(a1, b2, acc[1][2]); acc[1][3] = ffma2(a1, b3, acc[1][3]);
            acc[2][0] = ffma2(a2, b0, acc[2][0]); acc[2][1] = ffma2(a2, b1, acc[2][1]);
            acc[2][2] = ffma2(a2, b2, acc[2][2]); acc[2][3] = ffma2(a2, b3, acc[2][3]);
            acc[3][0] = ffma2(a3, b0, acc[3][0]); acc[3][1] = ffma2(a3, b1, acc[3][1]);
            acc[3][2] = ffma2(a3, b2, acc[3][2]); acc[3][3] = ffma2(a3, b3, acc[3][3]);
        }
        __syncthreads();
    }
    const int nc = n0 + (tn << 3);
    float4 bv0 = *reinterpret_cast<const float4*>(bias + nc);
    float4 bv1 = *reinterpret_cast<const float4*>(bias + nc + 4);
#pragma unroll
    for (int i = 0; i < 4; i++) {
        int r = m0 + (tm << 2) + i;                   // r = b*T + t
        int orow = ((r & (TT - 1)) << 6) + (r >> 9);  // t*64 + b
        float2 p0 = unpack2(acc[i][0]), p1 = unpack2(acc[i][1]);
        float2 p2 = unpack2(acc[i][2]), p3 = unpack2(acc[i][3]);
        float4 o0, o1;
        o0.x = p0.x + bv0.x; o0.y = p0.y + bv0.y; o0.z = p1.x + bv0.z; o0.w = p1.y + bv0.w;
        o1.x = p2.x + bv1.x; o1.y = p2.y + bv1.y; o1.z = p3.x + bv1.z; o1.w = p3.y + bv1.w;
        float* dst = g_xw + (size_t)orow * G4 + nc;
        *reinterpret_cast<float4*>(dst)     = o0;
        *reinterpret_cast<float4*>(dst + 4) = o1;
    }
}

// GEMM 2: g_xw[t*64+b][n] = bn(h1)[t,b,:] @ Wx2 + b2  (block m = one timestep)
__global__ __launch_bounds__(256) void gemm_xw2(const float* __restrict__ W,
                                                const float* __restrict__ bias) {
    __shared__ __align__(16) float As[16][68];    // [k][b]
    __shared__ __align__(16) float Bs[16][136];   // [k][n]
    const int tid = threadIdx.x;
    const int t = blockIdx.y;
    const int n0 = blockIdx.x * 128;
    const int tm = tid >> 4;
    const int tn = tid & 15;
    const float* Ab = g_h1 + (size_t)t * (HH * BB);
    unsigned long long acc[4][4] = {};
    for (int k0 = 0; k0 < HH; k0 += 16) {
        {   // A: 16k x 64b, BN applied per k-row
            int kk = tid >> 4, bq = (tid & 15) << 2;
            float s = g_scale[k0 + kk], sh = g_shift[k0 + kk];
            float4 v = *reinterpret_cast<const float4*>(Ab + (size_t)(k0 + kk) * BB + bq);
            v.x = v.x * s + sh; v.y = v.y * s + sh;
            v.z = v.z * s + sh; v.w = v.w * s + sh;
            *reinterpret_cast<float4*>(&As[kk][bq]) = v;
        }
        {   // B: 16k x 128n
            int kk = tid >> 4, c = (tid & 15) << 3;
            const float* src = W + (size_t)(k0 + kk) * G4 + n0 + c;
            float4 v0 = *reinterpret_cast<const float4*>(src);
            float4 v1 = *reinterpret_cast<const float4*>(src + 4);
            *reinterpret_cast<float4*>(&Bs[kk][c])     = v0;
            *reinterpret_cast<float4*>(&Bs[kk][c + 4]) = v1;
        }
        __syncthreads();
#pragma unroll
        for (int k = 0; k < 16; k++) {
            float4 a = *reinterpret_cast<const float4*>(&As[k][tm << 2]);
            const unsigned long long* bp =
                reinterpret_cast<const unsigned long long*>(&Bs[k][tn << 3]);
            unsigned long long b0 = bp[0], b1 = bp[1], b2 = bp[2], b3 = bp[3];
            unsigned long long a0 = pack2(a.x, a.x), a1 = pack2(a.y, a.y);
            unsigned long long a2 = pack2(a.z, a.z), a3 = pack2(a.w, a.w);
            acc[0][0] = ffma2(a0, b0, acc[0][0]); acc[0][1] = ffma2(a0, b1, acc[0][1]);
            acc[0][2] = ffma2(a0, b2, acc[0][2]); acc[0][3] = ffma2(a0, b3, acc[0][3]);
            acc[1][0] = ffma2(a1, b0, acc[1][0]); acc[1][1] = ffma2(a1, b1, acc[1][1]);
            acc[1][2] = ffma2(a1, b2, acc[1][2]); acc[1][3] = ffma2(a1, b3, acc[1][3]);
            acc[2][0] = ffma2(a2, b0, acc[2][0]); acc[2][1] = ffma2(a2, b1, acc[2][1]);
            acc[2][2] = ffma2(a2, b2, acc[2][2]); acc[2][3] = ffma2(a2, b3, acc[2][3]);
            acc[3][0] = ffma2(a3, b0, acc[3][0]); acc[3][1] = ffma2(a3, b1, acc[3][1]);
            acc[3][2] = ffma2(a3, b2, acc[3][2]); acc[3][3] = ffma2(a3, b3, acc[3][3]);
        }
        __syncthreads();
    }
    const int nc = n0 + (tn << 3);
    float4 bv0 = *reinterpret_cast<const float4*>(bias + nc);
    float4 bv1 = *reinterpret_cast<const float4*>(bias + nc + 4);
#pragma unroll
    for (int i = 0; i < 4; i++) {
        int orow = t * 64 + (tm << 2) + i;            // row = batch within t
        float2 p0 = unpack2(acc[i][0]), p1 = unpack2(acc[i][1]);
        float2 p2 = unpack2(acc[i][2]), p3 = unpack2(acc[i][3]);
        float4 o0, o1;
        o0.x = p0.x + bv0.x; o0.y = p0.y + bv0.y; o0.z = p1.x + bv0.z; o0.w = p1.y + bv0.w;
        o1.x = p2.x + bv1.x; o1.y = p2.y + bv1.y; o1.z = p3.x + bv1.z; o1.w = p3.y + bv1.w;
        float* dst = g_xw + (size_t)orow * G4 + nc;
        *reinterpret_cast<float4*>(dst)     = o0;
        *reinterpret_cast<float4*>(dst + 4) = o1;
    }
}

// ---------------- persistent LSTM layer (EXACT R12 — proven best) -----------------
// 128 blocks (32 clusters x 4 CTAs) x 512 threads. Block owns 4 units = 16 z-cols
// x 64 batches. Fill: 4-CTA TMA multicast, 16 KB slice per CTA per 64 KB chunk.
// smem: [w2 32KB][h_s 128KB][part 32KB][zb 4.25KB][2 mbar] = 200,976 B
#define SMEM_LSTM (32768 + 131072 + 32768 + 16 * 68 * 4 + 16)
__global__ __launch_bounds__(512) void lstm_layer(const float* __restrict__ Wh, int layer) {
    extern __shared__ __align__(16) char smem[];
    float2* w2  = reinterpret_cast<float2*>(smem);                 // [512][8] col-pairs
    float*  h_s = reinterpret_cast<float*>(smem + 32768);          // [512][64]
    float*  part = reinterpret_cast<float*>(smem + 163840);        // [8][8][64] f32x2
    float*  zb  = reinterpret_cast<float*>(smem + 196608);         // [16][68]
    const unsigned smem_base = (unsigned)__cvta_generic_to_shared(smem);
    const unsigned hsa  = smem_base + 32768;
    const unsigned bar0 = smem_base + 200960;
    const unsigned bar1 = smem_base + 200968;

    const int tid = threadIdx.x;
    const int lane = tid & 31;
    const int w = tid >> 5;                 // warp 0..15
    const int wj = w & 1, wk = w >> 1;
    const int u0 = blockIdx.x << 2;
    float* hseq = layer ? g_h2 : g_h1;
    unsigned* bar = &g_bar[layer];

    unsigned int rank;
    asm("mov.u32 %0, %%cluster_ctarank;" : "=r"(rank));
    const unsigned slice_off = rank * 16384u;      // this CTA's quarter of a chunk

    // epilogue mapping (tid < 256)
    const int u2 = (tid >> 6) & 3, b_e = tid & 63;
    const size_t sidx = (size_t)(u0 + u2) * BB + b_e;
    float c_reg = 0.f;

    // reducer mapping: thread -> (jpg: col-pair 0..7, br: batch 0..63)
    const int jpg = tid >> 6;
    const int br = tid & 63;
    const int xcol = ((jpg >> 1) * HH) + u0 + ((jpg & 1) * 2);  // col of j=2*jpg

    // mbarriers (count = 1: the local expect_tx arrival)
    if (tid == 0) {
        asm volatile("mbarrier.init.shared.b64 [%0], 1;" :: "r"(bar0) : "memory");
        asm volatile("mbarrier.init.shared.b64 [%0], 1;" :: "r"(bar1) : "memory");
    }

    // one-time: Wh slice as natural f32x2 col-pairs: w2[k][jp] = (Wh[k][c], Wh[k][c+1])
    for (int idx = tid; idx < 512 * 8; idx += 512) {
        int k = idx >> 3, jp = idx & 7;
        int col = ((jp >> 1) * HH) + u0 + ((jp & 1) * 2);
        const float* p = Wh + (size_t)k * G4 + col;
        w2[idx] = make_float2(__ldg(p), __ldg(p + 1));
    }
    __syncthreads();   // mbarrier init + w2 visible within CTA

    // cluster sync: peers' mbarriers must be live before any multicast lands
    asm volatile("barrier.cluster.arrive.aligned;" ::: "memory");
    asm volatile("barrier.cluster.wait.aligned;" ::: "memory");

    // prefetch xw for t=0
    unsigned long long nxw;
    {
        float2 v = __ldg(reinterpret_cast<const float2*>(g_xw + (size_t)br * G4 + xcol));
        nxw = pack2(v.x, v.y);
    }

    for (int t = 0; t < TT; t++) {
        const float* hin = g_hT[t & 1];
        float* hout = g_hT[(t & 1) ^ 1];
        const unsigned parity = (unsigned)(t & 1);
        const char* hinb = reinterpret_cast<const char*>(hin);

        // multicast bulk-TMA h fill: chunk A (k<256) and chunk B, 16 KB slice each.
        if (tid == 0) {
            asm volatile("mbarrier.arrive.expect_tx.shared.b64 _, [%0], %1;"
                         :: "r"(bar0), "r"(65536u) : "memory");
            asm volatile(
                "cp.async.bulk.shared::cluster.global.mbarrier::complete_tx::bytes"
                ".multicast::cluster [%0], [%1], %2, [%3], %4;"
                :: "r"(hsa + slice_off), "l"(hinb + slice_off),
                   "r"(16384u), "r"(bar0), "h"((unsigned short)0xF) : "memory");
            asm volatile("mbarrier.arrive.expect_tx.shared.b64 _, [%0], %1;"
                         :: "r"(bar1), "r"(65536u) : "memory");
            asm volatile(
                "cp.async.bulk.shared::cluster.global.mbarrier::complete_tx::bytes"
                ".multicast::cluster [%0], [%1], %2, [%3], %4;"
                :: "r"(hsa + 65536u + slice_off), "l"(hinb + 65536 + slice_off),
                   "r"(16384u), "r"(bar1), "h"((unsigned short)0xF) : "memory");
        }

        unsigned long long curxw = nxw;
        if (t + 1 < TT) {
            float2 v = __ldg(reinterpret_cast<const float2*>(
                g_xw + (size_t)(t + 1) * (BB * G4) + (size_t)br * G4 + xcol));
            nxw = pack2(v.x, v.y);
        }

        unsigned long long acc0 = 0, acc1 = 0, acc2 = 0, acc3 = 0;
        unsigned long long acc4 = 0, acc5 = 0, acc6 = 0, acc7 = 0;

#define COMPUTE_KS(kbase)                                                        \
        _Pragma("unroll 8")                                                      \
        for (int kk = 0; kk < 32; kk++) {                                        \
            int k = (kbase) + kk;                                               \
            float2 h2 = *reinterpret_cast<const float2*>(h_s + k * 64 + (lane << 1)); \
            unsigned long long hd0 = pack2(h2.x, h2.x);                          \
            unsigned long long hd1 = pack2(h2.y, h2.y);                          \
            const ulonglong2* wp = reinterpret_cast<const ulonglong2*>(w2 + k * 8 + (wj << 2)); \
            ulonglong2 wva = wp[0];                                              \
            ulonglong2 wvb = wp[1];                                              \
            acc0 = ffma2(wva.x, hd0, acc0); acc1 = ffma2(wva.x, hd1, acc1);      \
            acc2 = ffma2(wva.y, hd0, acc2); acc3 = ffma2(wva.y, hd1, acc3);      \
            acc4 = ffma2(wvb.x, hd0, acc4); acc5 = ffma2(wvb.x, hd1, acc5);      \
            acc6 = ffma2(wvb.y, hd0, acc6); acc7 = ffma2(wvb.y, hd1, acc7);      \
        }

        mbar_wait(bar0, parity);                   // chunk A (k < 256) landed
        COMPUTE_KS(wk * 32)                        // A-part: k in [32wk, 32wk+32)

        mbar_wait(bar1, parity);                   // chunk B landed
        COMPUTE_KS(256 + wk * 32)                  // B-part

        // write k-partials: part[wk][jp][b] f32x2; wk stride = 1024 floats (4 KB)
        {
            float* pb = part + wk * 1024 + (wj << 2) * 128 + (lane << 2);
            ulonglong2 v0; v0.x = acc0; v0.y = acc1;
            ulonglong2 v1; v1.x = acc2; v1.y = acc3;
            ulonglong2 v2; v2.x = acc4; v2.y = acc5;
            ulonglong2 v3; v3.x = acc6; v3.y = acc7;
            *reinterpret_cast<ulonglong2*>(pb)       = v0;
            *reinterpret_cast<ulonglong2*>(pb + 128) = v1;
            *reinterpret_cast<ulonglong2*>(pb + 256) = v2;
            *reinterpret_cast<ulonglong2*>(pb + 384) = v3;
        }
        __syncthreads();

        // reduce over 8 k-slices, deterministic: z = xw + sum_{wk=0..7} part
        {
            unsigned long long s = curxw;
            const float* pr = part + jpg * 128 + (br << 1);
#pragma unroll
            for (int q = 0; q < 8; q++) {
                unsigned long long p = *reinterpret_cast<const unsigned long long*>(pr + q * 1024);
                s = addf2(s, p);
            }
            float2 sf = unpack2(s);
            zb[(jpg << 1) * 68 + br]       = sf.x;
            zb[((jpg << 1) + 1) * 68 + br] = sf.y;
        }
        __syncthreads();

        // gates + state update (256 threads: 4 units x 64 batches)
        if (tid < 256) {
            float zi = zb[u2 * 68 + b_e],        zf = zb[(4 + u2) * 68 + b_e];
            float zg = zb[(8 + u2) * 68 + b_e],  zo = zb[(12 + u2) * 68 + b_e];
            float ig = 1.f / (1.f + expf(-zi));
            float fg = 1.f / (1.f + expf(-zf));
            float og = 1.f / (1.f + expf(-zo));
            float gg = tanhf(zg);
            c_reg = fg * c_reg + ig * gg;
            float hn = og * tanhf(c_reg);
            hout[sidx] = hn;
            hseq[(size_t)t * (HH * BB) + sidx] = hn;
        }
        // grid barrier: all blocks finish hout before next step
        __threadfence();
        __syncthreads();
        if (tid == 0) {
            atomicAdd(bar, 1u);
            unsigned target = (unsigned)(t + 1) * 128u;
            while (*(volatile unsigned*)bar < target) { __nanosleep(16); }
        }
        __syncthreads();
#undef COMPUTE_KS
    }

    // cluster sync before exit: no CTA leaves while peers' multicasts could target it
    asm volatile("barrier.cluster.arrive.aligned;" ::: "memory");
    asm volatile("barrier.cluster.wait.aligned;" ::: "memory");
}

// ---------------- BN stats (training mode), folded scale/shift, deterministic -------
__global__ __launch_bounds__(256) void bn_stats(int layer, const float* __restrict__ gamma,
                                                const float* __restrict__ beta) {
    const float* h = layer ? g_h2 : g_h1;
    const int kf = blockIdx.x;
    const int tid = threadIdx.x;
    float s = 0.f, ss = 0.f;
    for (int lin = tid; lin < NR; lin += 256) {
        float v = h[(size_t)(lin >> 6) * (HH * BB) + (size_t)kf * BB + (lin & 63)];
        s += v; ss += v * v;
    }
    __shared__ float rs[256], rq[256];
    rs[tid] = s; rq[tid] = ss;
    __syncthreads();
    for (int off = 128; off > 0; off >>= 1) {
        if (tid < off) { rs[tid] += rs[tid + off]; rq[tid] += rq[tid + off]; }
        __syncthreads();
    }
    if (tid == 0) {
        float mean = rs[0] * (1.f / 32768.f);
        float var = rq[0] * (1.f / 32768.f) - mean * mean;
        float rstd = rsqrtf(var + 1e-5f);
        float sc = rstd * gamma[kf];
        g_scale[layer * HH + kf] = sc;
        g_shift[layer * HH + kf] = beta[kf] - mean * sc;
    }
}

// ---------------- Dense head ----------------
__global__ __launch_bounds__(256) void dense_out(const float* __restrict__ Wd1,
                                                 const float* __restrict__ bd1,
                                                 const float* __restrict__ Wd2,
                                                 const float* __restrict__ bd2,
                                                 float* __restrict__ out) {
    __shared__ float hs[64][68];
    __shared__ float ws[64][16];
    __shared__ float sp[4][64];
    const int t = blockIdx.x, tid = threadIdx.x;
    const int b = tid & 63, jg = tid >> 6;
    float a0 = 0.f, a1 = 0.f, a2 = 0.f, a3 = 0.f;
    for (int k0 = 0; k0 < HH; k0 += 64) {
#pragma unroll
        for (int i = 0; i < 16; i++) {
            int lin = tid + i * 256; int k = lin >> 6, bb = lin & 63;
            float v = g_h2[(size_t)t * (HH * BB) + (size_t)(k0 + k) * BB + bb];
            hs[k][bb] = v * g_scale[HH + k0 + k] + g_shift[HH + k0 + k];
        }
#pragma unroll
        for (int i = 0; i < 4; i++) {
            int lin = tid + i * 256; int jj = lin & 15, k = lin >> 4;
            ws[k][jj] = Wd1[(size_t)(k0 + k) * 16 + jj];
        }
        __syncthreads();
#pragma unroll
        for (int k = 0; k < 64; k++) {
            float hv = hs[k][b];
            a0 += hv * ws[k][jg * 4 + 0];
            a1 += hv * ws[k][jg * 4 + 1];
            a2 += hv * ws[k][jg * 4 + 2];
            a3 += hv * ws[k][jg * 4 + 3];
        }
        __syncthreads();
    }
    float p = fmaxf(a0 + bd1[jg * 4 + 0], 0.f) * Wd2[jg * 4 + 0]
            + fmaxf(a1 + bd1[jg * 4 + 1], 0.f) * Wd2[jg * 4 + 1]
            + fmaxf(a2 + bd1[jg * 4 + 2], 0.f) * Wd2[jg * 4 + 2]
            + fmaxf(a3 + bd1[jg * 4 + 3], 0.f) * Wd2[jg * 4 + 3];
    sp[jg][b] = p;
    __syncthreads();
    if (tid < 64) {
        out[(size_t)tid * TT + t] = sp[0][tid] + sp[1][tid] + sp[2][tid] + sp[3][tid] + bd2[0];
    }
}

// ---------------- launch (9 graph nodes) ----------------
extern "C" void kernel_launch(void* const* d_in, const int* in_sizes, int n_in,
                              void* d_out, int out_size) {
    const float* x   = (const float*)d_in[0];
    const float* Wx1 = (const float*)d_in[1];
    const float* Wh1 = (const float*)d_in[2];
    const float* b1  = (const float*)d_in[3];
    const float* g1  = (const float*)d_in[4];
    const float* be1 = (const float*)d_in[5];
    const float* Wx2 = (const float*)d_in[6];
    const float* Wh2 = (const float*)d_in[7];
    const float* b2  = (const float*)d_in[8];
    const float* g2  = (const float*)d_in[9];
    const float* be2 = (const float*)d_in[10];
    const float* Wd1 = (const float*)d_in[11];
    const float* bd1 = (const float*)d_in[12];
    const float* Wd2 = (const float*)d_in[13];
    const float* bd2 = (const float*)d_in[14];
    float* out = (float*)d_out;

    static bool attr_set = false;
    if (!attr_set) {
        cudaFuncSetAttribute(lstm_layer, cudaFuncAttributeMaxDynamicSharedMemorySize, SMEM_LSTM);
        attr_set = true;
    }

    // cluster launch config for the scans (4-CTA clusters for TMA multicast)
    cudaLaunchConfig_t cfg = {};
    cfg.gridDim = dim3(128, 1, 1);
    cfg.blockDim = dim3(512, 1, 1);
    cfg.dynamicSmemBytes = SMEM_LSTM;
    cfg.stream = 0;
    cudaLaunchAttribute attrs[1];
    attrs[0].id = cudaLaunchAttributeClusterDimension;
    attrs[0].val.clusterDim = {4, 1, 1};
    cfg.attrs = attrs;
    cfg.numAttrs = 1;

    zero_state<<<64, 512>>>();
    gemm_xw1<<<dim3(16, 512), 256>>>(x, Wx1, b1);
    cudaLaunchKernelEx(&cfg, lstm_layer, Wh1, 0);
    bn_stats<<<512, 256>>>(0, g1, be1);
    gemm_xw2<<<dim3(16, 512), 256>>>(Wx2, b2);
    zero_state<<<64, 512>>>();
    cudaLaunchKernelEx(&cfg, lstm_layer, Wh2, 1);
    bn_stats<<<512, 256>>>(1, g2, be2);
    dense_out<<<512, 256>>>(Wd1, bd1, Wd2, bd2, out);
}

// round 16
// speedup vs baseline: 1.0799x; 1.0799x over previous
#include <cuda_runtime.h>
#include <math.h>

#define BB 64      // batch
#define TT 512     // seq len
#define FF 128     // input features
#define HH 512     // hidden
#define G4 2048    // 4*H
#define NR 32768   // B*T

// ---------------- scratch (device globals; no allocations) ----------------
__device__ float g_xw[(size_t)NR * G4];        // [t][b][4H]  (256 MB)
__device__ float g_h1[(size_t)TT * HH * BB];   // [t][k][b]   (64 MB)
__device__ float g_h2[(size_t)TT * HH * BB];   // [t][k][b]
__device__ __align__(128) float g_hT[2][HH * BB];  // ping-pong h state, [k][b]
__device__ float g_scale[2 * HH];              // BN folded scale per layer
__device__ float g_shift[2 * HH];              // BN folded shift per layer
__device__ unsigned g_bar[2];                  // grid barrier counters

// ---------------- packed f32x2 helpers (sm_103a dual-FMA path) ----------------
__device__ __forceinline__ unsigned long long pack2(float lo, float hi) {
    unsigned long long r;
    asm("mov.b64 %0, {%1, %2};" : "=l"(r) : "f"(lo), "f"(hi));
    return r;
}
__device__ __forceinline__ unsigned long long ffma2(unsigned long long a,
                                                    unsigned long long b,
                                                    unsigned long long c) {
    unsigned long long d;
    asm("fma.rn.f32x2 %0, %1, %2, %3;" : "=l"(d) : "l"(a), "l"(b), "l"(c));
    return d;
}
__device__ __forceinline__ unsigned long long addf2(unsigned long long a,
                                                    unsigned long long b) {
    unsigned long long d;
    asm("add.rn.f32x2 %0, %1, %2;" : "=l"(d) : "l"(a), "l"(b));
    return d;
}
__device__ __forceinline__ float2 unpack2(unsigned long long v) {
    float2 f;
    asm("mov.b64 {%0, %1}, %2;" : "=f"(f.x), "=f"(f.y) : "l"(v));
    return f;
}
// fast sigmoid / tanh on the MUFU.EX2 path (error ~1e-6 rel; budget is 1e-3)
__device__ __forceinline__ float fsig(float x) {
    return 1.f / (1.f + __expf(-x));
}
__device__ __forceinline__ float ftanh(float x) {
    return 2.f / (1.f + __expf(-2.f * x)) - 1.f;
}
// mbarrier wait (parity), acquire semantics for subsequent LDS reads
__device__ __forceinline__ void mbar_wait(unsigned mbar, unsigned parity) {
    asm volatile(
        "{\n\t"
        ".reg .pred P;\n\t"
        "LAB_WAIT_%=:\n\t"
        "mbarrier.try_wait.parity.acquire.cta.shared::cta.b64 P, [%0], %1, 0x989680;\n\t"
        "@P bra LAB_DONE_%=;\n\t"
        "bra LAB_WAIT_%=;\n\t"
        "LAB_DONE_%=:\n\t"
        "}"
        :: "r"(mbar), "r"(parity) : "memory");
}

// ---------------- zero h state + barrier counters ----------------
__global__ void zero_state() {
    int idx = blockIdx.x * blockDim.x + threadIdx.x;
    if (idx < HH * BB) {
        g_hT[0][idx] = 0.f;
        g_hT[1][idx] = 0.f;
    }
    if (idx < 2) g_bar[idx] = 0u;
}

// ---------------- GEMM 1: g_xw[t*64+b][n] = x[b*T+t][:] @ Wx1 + b1 ----------------
__global__ __launch_bounds__(256) void gemm_xw1(const float* __restrict__ x,
                                                const float* __restrict__ W,
                                                const float* __restrict__ bias) {
    __shared__ __align__(16) float As[16][68];
    __shared__ __align__(16) float Bs[16][68];
    const int tid = threadIdx.x;
    const int m0 = blockIdx.y * 64;
    const int n0 = blockIdx.x * 64;
    const int tm = (tid >> 4) << 2;
    const int tn = (tid & 15) << 2;
    unsigned long long accL[4] = {}, accH[4] = {};
    for (int k0 = 0; k0 < FF; k0 += 16) {
        {
            int m = tid >> 2, q = tid & 3;
            float4 v = *reinterpret_cast<const float4*>(x + (size_t)(m0 + m) * FF + k0 + q * 4);
            As[q * 4 + 0][m] = v.x; As[q * 4 + 1][m] = v.y;
            As[q * 4 + 2][m] = v.z; As[q * 4 + 3][m] = v.w;
        }
        {
            int k = tid >> 4, c = (tid & 15) << 2;
            float4 v = *reinterpret_cast<const float4*>(W + (size_t)(k0 + k) * G4 + n0 + c);
            Bs[k][c] = v.x; Bs[k][c + 1] = v.y; Bs[k][c + 2] = v.z; Bs[k][c + 3] = v.w;
        }
        __syncthreads();
#pragma unroll
        for (int k = 0; k < 16; k++) {
            float4 a = *reinterpret_cast<const float4*>(&As[k][tm]);
            ulonglong2 bv = *reinterpret_cast<const ulonglong2*>(&Bs[k][tn]);
            unsigned long long a0 = pack2(a.x, a.x), a1 = pack2(a.y, a.y);
            unsigned long long a2 = pack2(a.z, a.z), a3 = pack2(a.w, a.w);
            accL[0] = ffma2(a0, bv.x, accL[0]); accH[0] = ffma2(a0, bv.y, accH[0]);
            accL[1] = ffma2(a1, bv.x, accL[1]); accH[1] = ffma2(a1, bv.y, accH[1]);
            accL[2] = ffma2(a2, bv.x, accL[2]); accH[2] = ffma2(a2, bv.y, accH[2]);
            accL[3] = ffma2(a3, bv.x, accL[3]); accH[3] = ffma2(a3, bv.y, accH[3]);
        }
        __syncthreads();
    }
    float4 bvb = *reinterpret_cast<const float4*>(bias + n0 + tn);
#pragma unroll
    for (int i = 0; i < 4; i++) {
        int r = m0 + tm + i;                          // r = b*T + t
        int orow = ((r & (TT - 1)) << 6) + (r >> 9);  // t*64 + b
        float2 lo = unpack2(accL[i]), hi = unpack2(accH[i]);
        float4 o;
        o.x = lo.x + bvb.x; o.y = lo.y + bvb.y;
        o.z = hi.x + bvb.z; o.w = hi.y + bvb.w;
        *reinterpret_cast<float4*>(g_xw + (size_t)orow * G4 + n0 + tn) = o;
    }
}

// ---------------- GEMM 2: g_xw[t*64+b][n] = bn(h1)[t,b,:] @ Wx2 + b2 ----------------
__global__ __launch_bounds__(256) void gemm_xw2(const float* __restrict__ W,
                                                const float* __restrict__ bias) {
    __shared__ __align__(16) float As[16][68];
    __shared__ __align__(16) float Bs[16][68];
    const int tid = threadIdx.x;
    const int t = blockIdx.y;
    const int n0 = blockIdx.x * 64;
    const int tm = (tid >> 4) << 2;
    const int tn = (tid & 15) << 2;
    const float* Ab = g_h1 + (size_t)t * (HH * BB);
    unsigned long long accL[4] = {}, accH[4] = {};
    for (int k0 = 0; k0 < HH; k0 += 16) {
        {
            int b = tid & 63, kk = tid >> 6;
#pragma unroll
            for (int s = 0; s < 4; s++) {
                int k = kk * 4 + s;
                float v = Ab[(size_t)(k0 + k) * BB + b];
                As[k][b] = v * g_scale[k0 + k] + g_shift[k0 + k];
            }
        }
        {
            int k = tid >> 4, c = (tid & 15) << 2;
            float4 v = *reinterpret_cast<const float4*>(W + (size_t)(k0 + k) * G4 + n0 + c);
            Bs[k][c] = v.x; Bs[k][c + 1] = v.y; Bs[k][c + 2] = v.z; Bs[k][c + 3] = v.w;
        }
        __syncthreads();
#pragma unroll
        for (int k = 0; k < 16; k++) {
            float4 a = *reinterpret_cast<const float4*>(&As[k][tm]);
            ulonglong2 bv = *reinterpret_cast<const ulonglong2*>(&Bs[k][tn]);
            unsigned long long a0 = pack2(a.x, a.x), a1 = pack2(a.y, a.y);
            unsigned long long a2 = pack2(a.z, a.z), a3 = pack2(a.w, a.w);
            accL[0] = ffma2(a0, bv.x, accL[0]); accH[0] = ffma2(a0, bv.y, accH[0]);
            accL[1] = ffma2(a1, bv.x, accL[1]); accH[1] = ffma2(a1, bv.y, accH[1]);
            accL[2] = ffma2(a2, bv.x, accL[2]); accH[2] = ffma2(a2, bv.y, accH[2]);
            accL[3] = ffma2(a3, bv.x, accL[3]); accH[3] = ffma2(a3, bv.y, accH[3]);
        }
        __syncthreads();
    }
    float4 bvb = *reinterpret_cast<const float4*>(bias + n0 + tn);
#pragma unroll
    for (int i = 0; i < 4; i++) {
        int orow = t * 64 + tm + i;
        float2 lo = unpack2(accL[i]), hi = unpack2(accH[i]);
        float4 o;
        o.x = lo.x + bvb.x; o.y = lo.y + bvb.y;
        o.z = hi.x + bvb.z; o.w = hi.y + bvb.w;
        *reinterpret_cast<float4*>(g_xw + (size_t)orow * G4 + n0 + tn) = o;
    }
}

// ---------------- persistent LSTM layer (R12 + fast gates ONLY) -------------------
// 128 blocks (32 clusters x 4 CTAs) x 512 threads. Block owns 4 units = 16 z-cols
// x 64 batches. Fill: 4-CTA TMA multicast, 16 KB slice per CTA per 64 KB chunk.
// smem: [w2 32KB][h_s 128KB][part 32KB][zb 4.25KB][2 mbar] = 200,976 B
#define SMEM_LSTM (32768 + 131072 + 32768 + 16 * 68 * 4 + 16)
__global__ __launch_bounds__(512) void lstm_layer(const float* __restrict__ Wh, int layer) {
    extern __shared__ __align__(16) char smem[];
    float2* w2  = reinterpret_cast<float2*>(smem);                 // [512][8] col-pairs
    float*  h_s = reinterpret_cast<float*>(smem + 32768);          // [512][64]
    float*  part = reinterpret_cast<float*>(smem + 163840);        // [8][8][64] f32x2
    float*  zb  = reinterpret_cast<float*>(smem + 196608);         // [16][68]
    const unsigned smem_base = (unsigned)__cvta_generic_to_shared(smem);
    const unsigned hsa  = smem_base + 32768;
    const unsigned bar0 = smem_base + 200960;
    const unsigned bar1 = smem_base + 200968;

    const int tid = threadIdx.x;
    const int lane = tid & 31;
    const int w = tid >> 5;                 // warp 0..15
    const int wj = w & 1, wk = w >> 1;
    const int u0 = blockIdx.x << 2;
    float* hseq = layer ? g_h2 : g_h1;
    unsigned* bar = &g_bar[layer];

    unsigned int rank;
    asm("mov.u32 %0, %%cluster_ctarank;" : "=r"(rank));
    const unsigned slice_off = rank * 16384u;      // this CTA's quarter of a chunk

    // epilogue mapping (tid < 256)
    const int u2 = (tid >> 6) & 3, b_e = tid & 63;
    const size_t sidx = (size_t)(u0 + u2) * BB + b_e;
    float c_reg = 0.f;

    // reducer mapping: thread -> (jpg: col-pair 0..7, br: batch 0..63)
    const int jpg = tid >> 6;
    const int br = tid & 63;
    const int xcol = ((jpg >> 1) * HH) + u0 + ((jpg & 1) * 2);  // col of j=2*jpg

    // mbarriers (count = 1: the local expect_tx arrival)
    if (tid == 0) {
        asm volatile("mbarrier.init.shared.b64 [%0], 1;" :: "r"(bar0) : "memory");
        asm volatile("mbarrier.init.shared.b64 [%0], 1;" :: "r"(bar1) : "memory");
    }

    // one-time: Wh slice as natural f32x2 col-pairs: w2[k][jp] = (Wh[k][c], Wh[k][c+1])
    for (int idx = tid; idx < 512 * 8; idx += 512) {
        int k = idx >> 3, jp = idx & 7;
        int col = ((jp >> 1) * HH) + u0 + ((jp & 1) * 2);
        const float* p = Wh + (size_t)k * G4 + col;
        w2[idx] = make_float2(__ldg(p), __ldg(p + 1));
    }
    __syncthreads();   // mbarrier init + w2 visible within CTA

    // cluster sync: peers' mbarriers must be live before any multicast lands
    asm volatile("barrier.cluster.arrive.aligned;" ::: "memory");
    asm volatile("barrier.cluster.wait.aligned;" ::: "memory");

    // prefetch xw for t=0
    unsigned long long nxw;
    {
        float2 v = __ldg(reinterpret_cast<const float2*>(g_xw + (size_t)br * G4 + xcol));
        nxw = pack2(v.x, v.y);
    }

    for (int t = 0; t < TT; t++) {
        const float* hin = g_hT[t & 1];
        float* hout = g_hT[(t & 1) ^ 1];
        const unsigned parity = (unsigned)(t & 1);
        const char* hinb = reinterpret_cast<const char*>(hin);

        // multicast bulk-TMA h fill: chunk A (k<256) and chunk B, 16 KB slice each.
        if (tid == 0) {
            asm volatile("mbarrier.arrive.expect_tx.shared.b64 _, [%0], %1;"
                         :: "r"(bar0), "r"(65536u) : "memory");
            asm volatile(
                "cp.async.bulk.shared::cluster.global.mbarrier::complete_tx::bytes"
                ".multicast::cluster [%0], [%1], %2, [%3], %4;"
                :: "r"(hsa + slice_off), "l"(hinb + slice_off),
                   "r"(16384u), "r"(bar0), "h"((unsigned short)0xF) : "memory");
            asm volatile("mbarrier.arrive.expect_tx.shared.b64 _, [%0], %1;"
                         :: "r"(bar1), "r"(65536u) : "memory");
            asm volatile(
                "cp.async.bulk.shared::cluster.global.mbarrier::complete_tx::bytes"
                ".multicast::cluster [%0], [%1], %2, [%3], %4;"
                :: "r"(hsa + 65536u + slice_off), "l"(hinb + 65536 + slice_off),
                   "r"(16384u), "r"(bar1), "h"((unsigned short)0xF) : "memory");
        }

        unsigned long long curxw = nxw;
        if (t + 1 < TT) {
            float2 v = __ldg(reinterpret_cast<const float2*>(
                g_xw + (size_t)(t + 1) * (BB * G4) + (size_t)br * G4 + xcol));
            nxw = pack2(v.x, v.y);
        }

        unsigned long long acc0 = 0, acc1 = 0, acc2 = 0, acc3 = 0;
        unsigned long long acc4 = 0, acc5 = 0, acc6 = 0, acc7 = 0;

#define COMPUTE_KS(kbase)                                                        \
        _Pragma("unroll 8")                                                      \
        for (int kk = 0; kk < 32; kk++) {                                        \
            int k = (kbase) + kk;                                               \
            float2 h2 = *reinterpret_cast<const float2*>(h_s + k * 64 + (lane << 1)); \
            unsigned long long hd0 = pack2(h2.x, h2.x);                          \
            unsigned long long hd1 = pack2(h2.y, h2.y);                          \
            const ulonglong2* wp = reinterpret_cast<const ulonglong2*>(w2 + k * 8 + (wj << 2)); \
            ulonglong2 wva = wp[0];                                              \
            ulonglong2 wvb = wp[1];                                              \
            acc0 = ffma2(wva.x, hd0, acc0); acc1 = ffma2(wva.x, hd1, acc1);      \
            acc2 = ffma2(wva.y, hd0, acc2); acc3 = ffma2(wva.y, hd1, acc3);      \
            acc4 = ffma2(wvb.x, hd0, acc4); acc5 = ffma2(wvb.x, hd1, acc5);      \
            acc6 = ffma2(wvb.y, hd0, acc6); acc7 = ffma2(wvb.y, hd1, acc7);      \
        }

        mbar_wait(bar0, parity);                   // chunk A (k < 256) landed
        COMPUTE_KS(wk * 32)                        // A-part: k in [32wk, 32wk+32)

        mbar_wait(bar1, parity);                   // chunk B landed
        COMPUTE_KS(256 + wk * 32)                  // B-part

        // write k-partials: part[wk][jp][b] f32x2; wk stride = 1024 floats (4 KB)
        {
            float* pb = part + wk * 1024 + (wj << 2) * 128 + (lane << 2);
            ulonglong2 v0; v0.x = acc0; v0.y = acc1;
            ulonglong2 v1; v1.x = acc2; v1.y = acc3;
            ulonglong2 v2; v2.x = acc4; v2.y = acc5;
            ulonglong2 v3; v3.x = acc6; v3.y = acc7;
            *reinterpret_cast<ulonglong2*>(pb)       = v0;
            *reinterpret_cast<ulonglong2*>(pb + 128) = v1;
            *reinterpret_cast<ulonglong2*>(pb + 256) = v2;
            *reinterpret_cast<ulonglong2*>(pb + 384) = v3;
        }
        __syncthreads();

        // reduce over 8 k-slices, deterministic: z = xw + sum_{wk=0..7} part
        {
            unsigned long long s = curxw;
            const float* pr = part + jpg * 128 + (br << 1);
#pragma unroll
            for (int q = 0; q < 8; q++) {
                unsigned long long p = *reinterpret_cast<const unsigned long long*>(pr + q * 1024);
                s = addf2(s, p);
            }
            float2 sf = unpack2(s);
            zb[(jpg << 1) * 68 + br]       = sf.x;
            zb[((jpg << 1) + 1) * 68 + br] = sf.y;
        }
        __syncthreads();

        // gates + state update (256 threads: 4 units x 64 batches), MUFU fast path
        if (tid < 256) {
            float zi = zb[u2 * 68 + b_e],        zf = zb[(4 + u2) * 68 + b_e];
            float zg = zb[(8 + u2) * 68 + b_e],  zo = zb[(12 + u2) * 68 + b_e];
            float ig = fsig(zi);
            float fg = fsig(zf);
            float og = fsig(zo);
            float gg = ftanh(zg);
            c_reg = fg * c_reg + ig * gg;
            float hn = og * ftanh(c_reg);
            hout[sidx] = hn;
            hseq[(size_t)t * (HH * BB) + sidx] = hn;
        }
        // grid barrier: all blocks finish hout before next step
        __threadfence();
        __syncthreads();
        if (tid == 0) {
            atomicAdd(bar, 1u);
            unsigned target = (unsigned)(t + 1) * 128u;
            while (*(volatile unsigned*)bar < target) { __nanosleep(16); }
        }
        __syncthreads();
#undef COMPUTE_KS
    }

    // cluster sync before exit: no CTA leaves while peers' multicasts could target it
    asm volatile("barrier.cluster.arrive.aligned;" ::: "memory");
    asm volatile("barrier.cluster.wait.aligned;" ::: "memory");
}

// ---------------- BN stats (training mode), folded scale/shift, deterministic -------
__global__ __launch_bounds__(256) void bn_stats(int layer, const float* __restrict__ gamma,
                                                const float* __restrict__ beta) {
    const float* h = layer ? g_h2 : g_h1;
    const int kf = blockIdx.x;
    const int tid = threadIdx.x;
    float s = 0.f, ss = 0.f;
    for (int lin = tid; lin < NR; lin += 256) {
        float v = h[(size_t)(lin >> 6) * (HH * BB) + (size_t)kf * BB + (lin & 63)];
        s += v; ss += v * v;
    }
    __shared__ float rs[256], rq[256];
    rs[tid] = s; rq[tid] = ss;
    __syncthreads();
    for (int off = 128; off > 0; off >>= 1) {
        if (tid < off) { rs[tid] += rs[tid + off]; rq[tid] += rq[tid + off]; }
        __syncthreads();
    }
    if (tid == 0) {
        float mean = rs[0] * (1.f / 32768.f);
        float var = rq[0] * (1.f / 32768.f) - mean * mean;
        float rstd = rsqrtf(var + 1e-5f);
        float sc = rstd * gamma[kf];
        g_scale[layer * HH + kf] = sc;
        g_shift[layer * HH + kf] = beta[kf] - mean * sc;
    }
}

// ---------------- Dense head ----------------
__global__ __launch_bounds__(256) void dense_out(const float* __restrict__ Wd1,
                                                 const float* __restrict__ bd1,
                                                 const float* __restrict__ Wd2,
                                                 const float* __restrict__ bd2,
                                                 float* __restrict__ out) {
    __shared__ float hs[64][68];
    __shared__ float ws[64][16];
    __shared__ float sp[4][64];
    const int t = blockIdx.x, tid = threadIdx.x;
    const int b = tid & 63, jg = tid >> 6;
    float a0 = 0.f, a1 = 0.f, a2 = 0.f, a3 = 0.f;
    for (int k0 = 0; k0 < HH; k0 += 64) {
#pragma unroll
        for (int i = 0; i < 16; i++) {
            int lin = tid + i * 256; int k = lin >> 6, bb = lin & 63;
            float v = g_h2[(size_t)t * (HH * BB) + (size_t)(k0 + k) * BB + bb];
            hs[k][bb] = v * g_scale[HH + k0 + k] + g_shift[HH + k0 + k];
        }
#pragma unroll
        for (int i = 0; i < 4; i++) {
            int lin = tid + i * 256; int jj = lin & 15, k = lin >> 4;
            ws[k][jj] = Wd1[(size_t)(k0 + k) * 16 + jj];
        }
        __syncthreads();
#pragma unroll
        for (int k = 0; k < 64; k++) {
            float hv = hs[k][b];
            a0 += hv * ws[k][jg * 4 + 0];
            a1 += hv * ws[k][jg * 4 + 1];
            a2 += hv * ws[k][jg * 4 + 2];
            a3 += hv * ws[k][jg * 4 + 3];
        }
        __syncthreads();
    }
    float p = fmaxf(a0 + bd1[jg * 4 + 0], 0.f) * Wd2[jg * 4 + 0]
            + fmaxf(a1 + bd1[jg * 4 + 1], 0.f) * Wd2[jg * 4 + 1]
            + fmaxf(a2 + bd1[jg * 4 + 2], 0.f) * Wd2[jg * 4 + 2]
            + fmaxf(a3 + bd1[jg * 4 + 3], 0.f) * Wd2[jg * 4 + 3];
    sp[jg][b] = p;
    __syncthreads();
    if (tid < 64) {
        out[(size_t)tid * TT + t] = sp[0][tid] + sp[1][tid] + sp[2][tid] + sp[3][tid] + bd2[0];
    }
}

// ---------------- launch (9 graph nodes) ----------------
extern "C" void kernel_launch(void* const* d_in, const int* in_sizes, int n_in,
                              void* d_out, int out_size) {
    const float* x   = (const float*)d_in[0];
    const float* Wx1 = (const float*)d_in[1];
    const float* Wh1 = (const float*)d_in[2];
    const float* b1  = (const float*)d_in[3];
    const float* g1  = (const float*)d_in[4];
    const float* be1 = (const float*)d_in[5];
    const float* Wx2 = (const float*)d_in[6];
    const float* Wh2 = (const float*)d_in[7];
    const float* b2  = (const float*)d_in[8];
    const float* g2  = (const float*)d_in[9];
    const float* be2 = (const float*)d_in[10];
    const float* Wd1 = (const float*)d_in[11];
    const float* bd1 = (const float*)d_in[12];
    const float* Wd2 = (const float*)d_in[13];
    const float* bd2 = (const float*)d_in[14];
    float* out = (float*)d_out;

    static bool attr_set = false;
    if (!attr_set) {
        cudaFuncSetAttribute(lstm_layer, cudaFuncAttributeMaxDynamicSharedMemorySize, SMEM_LSTM);
        attr_set = true;
    }

    // cluster launch config for the scans (4-CTA clusters for TMA multicast)
    cudaLaunchConfig_t cfg = {};
    cfg.gridDim = dim3(128, 1, 1);
    cfg.blockDim = dim3(512, 1, 1);
    cfg.dynamicSmemBytes = SMEM_LSTM;
    cfg.stream = 0;
    cudaLaunchAttribute attrs[1];
    attrs[0].id = cudaLaunchAttributeClusterDimension;
    attrs[0].val.clusterDim = {4, 1, 1};
    cfg.attrs = attrs;
    cfg.numAttrs = 1;

    zero_state<<<64, 512>>>();
    gemm_xw1<<<dim3(32, 512), 256>>>(x, Wx1, b1);
    cudaLaunchKernelEx(&cfg, lstm_layer, Wh1, 0);
    bn_stats<<<512, 256>>>(0, g1, be1);
    gemm_xw2<<<dim3(32, 512), 256>>>(Wx2, b2);
    zero_state<<<64, 512>>>();
    cudaLaunchKernelEx(&cfg, lstm_layer, Wh2, 1);
    bn_stats<<<512, 256>>>(1, g2, be2);
    dense_out<<<512, 256>>>(Wd1, bd1, Wd2, bd2, out);
}

// round 17
// speedup vs baseline: 1.0949x; 1.0139x over previous
#include <cuda_runtime.h>
#include <math.h>

#define BB 64      // batch
#define TT 512     // seq len
#define FF 128     // input features
#define HH 512     // hidden
#define G4 2048    // 4*H
#define NR 32768   // B*T

// ---------------- scratch (device globals; no allocations) ----------------
__device__ float g_xw[(size_t)NR * G4];        // [t][b][4H]  (256 MB)
__device__ float g_h1[(size_t)TT * HH * BB];   // [t][k][b]   (64 MB)
__device__ float g_h2[(size_t)TT * HH * BB];   // [t][k][b]
__device__ __align__(128) float g_hT[2][HH * BB];  // ping-pong h state, [k][b]
__device__ float g_scale[2 * HH];              // BN folded scale per layer
__device__ float g_shift[2 * HH];              // BN folded shift per layer
__device__ unsigned g_bar[2];                  // grid barrier counters

// ---------------- packed f32x2 helpers (sm_103a dual-FMA path) ----------------
__device__ __forceinline__ unsigned long long pack2(float lo, float hi) {
    unsigned long long r;
    asm("mov.b64 %0, {%1, %2};" : "=l"(r) : "f"(lo), "f"(hi));
    return r;
}
__device__ __forceinline__ unsigned long long ffma2(unsigned long long a,
                                                    unsigned long long b,
                                                    unsigned long long c) {
    unsigned long long d;
    asm("fma.rn.f32x2 %0, %1, %2, %3;" : "=l"(d) : "l"(a), "l"(b), "l"(c));
    return d;
}
__device__ __forceinline__ unsigned long long addf2(unsigned long long a,
                                                    unsigned long long b) {
    unsigned long long d;
    asm("add.rn.f32x2 %0, %1, %2;" : "=l"(d) : "l"(a), "l"(b));
    return d;
}
__device__ __forceinline__ float2 unpack2(unsigned long long v) {
    float2 f;
    asm("mov.b64 {%0, %1}, %2;" : "=f"(f.x), "=f"(f.y) : "l"(v));
    return f;
}
// mbarrier wait (parity), acquire semantics for subsequent LDS reads
__device__ __forceinline__ void mbar_wait(unsigned mbar, unsigned parity) {
    asm volatile(
        "{\n\t"
        ".reg .pred P;\n\t"
        "LAB_WAIT_%=:\n\t"
        "mbarrier.try_wait.parity.acquire.cta.shared::cta.b64 P, [%0], %1, 0x989680;\n\t"
        "@P bra LAB_DONE_%=;\n\t"
        "bra LAB_WAIT_%=;\n\t"
        "LAB_DONE_%=:\n\t"
        "}"
        :: "r"(mbar), "r"(parity) : "memory");
}

// ---------------- zero h state + barrier counters ----------------
__global__ void zero_state() {
    int idx = blockIdx.x * blockDim.x + threadIdx.x;
    if (idx < HH * BB) {
        g_hT[0][idx] = 0.f;
        g_hT[1][idx] = 0.f;
    }
    if (idx < 2) g_bar[idx] = 0u;
}

// ---------------- GEMM 1: g_xw[t*64+b][n] = x[b*T+t][:] @ Wx1 + b1 ----------------
__global__ __launch_bounds__(256) void gemm_xw1(const float* __restrict__ x,
                                                const float* __restrict__ W,
                                                const float* __restrict__ bias) {
    __shared__ __align__(16) float As[16][68];
    __shared__ __align__(16) float Bs[16][68];
    const int tid = threadIdx.x;
    const int m0 = blockIdx.y * 64;
    const int n0 = blockIdx.x * 64;
    const int tm = (tid >> 4) << 2;
    const int tn = (tid & 15) << 2;
    unsigned long long accL[4] = {}, accH[4] = {};
    for (int k0 = 0; k0 < FF; k0 += 16) {
        {
            int m = tid >> 2, q = tid & 3;
            float4 v = *reinterpret_cast<const float4*>(x + (size_t)(m0 + m) * FF + k0 + q * 4);
            As[q * 4 + 0][m] = v.x; As[q * 4 + 1][m] = v.y;
            As[q * 4 + 2][m] = v.z; As[q * 4 + 3][m] = v.w;
        }
        {
            int k = tid >> 4, c = (tid & 15) << 2;
            float4 v = *reinterpret_cast<const float4*>(W + (size_t)(k0 + k) * G4 + n0 + c);
            Bs[k][c] = v.x; Bs[k][c + 1] = v.y; Bs[k][c + 2] = v.z; Bs[k][c + 3] = v.w;
        }
        __syncthreads();
#pragma unroll
        for (int k = 0; k < 16; k++) {
            float4 a = *reinterpret_cast<const float4*>(&As[k][tm]);
            ulonglong2 bv = *reinterpret_cast<const ulonglong2*>(&Bs[k][tn]);
            unsigned long long a0 = pack2(a.x, a.x), a1 = pack2(a.y, a.y);
            unsigned long long a2 = pack2(a.z, a.z), a3 = pack2(a.w, a.w);
            accL[0] = ffma2(a0, bv.x, accL[0]); accH[0] = ffma2(a0, bv.y, accH[0]);
            accL[1] = ffma2(a1, bv.x, accL[1]); accH[1] = ffma2(a1, bv.y, accH[1]);
            accL[2] = ffma2(a2, bv.x, accL[2]); accH[2] = ffma2(a2, bv.y, accH[2]);
            accL[3] = ffma2(a3, bv.x, accL[3]); accH[3] = ffma2(a3, bv.y, accH[3]);
        }
        __syncthreads();
    }
    float4 bvb = *reinterpret_cast<const float4*>(bias + n0 + tn);
#pragma unroll
    for (int i = 0; i < 4; i++) {
        int r = m0 + tm + i;                          // r = b*T + t
        int orow = ((r & (TT - 1)) << 6) + (r >> 9);  // t*64 + b
        float2 lo = unpack2(accL[i]), hi = unpack2(accH[i]);
        float4 o;
        o.x = lo.x + bvb.x; o.y = lo.y + bvb.y;
        o.z = hi.x + bvb.z; o.w = hi.y + bvb.w;
        *reinterpret_cast<float4*>(g_xw + (size_t)orow * G4 + n0 + tn) = o;
    }
}

// ---------------- GEMM 2: g_xw[t*64+b][n] = bn(h1)[t,b,:] @ Wx2 + b2 ----------------
__global__ __launch_bounds__(256) void gemm_xw2(const float* __restrict__ W,
                                                const float* __restrict__ bias) {
    __shared__ __align__(16) float As[16][68];
    __shared__ __align__(16) float Bs[16][68];
    const int tid = threadIdx.x;
    const int t = blockIdx.y;
    const int n0 = blockIdx.x * 64;
    const int tm = (tid >> 4) << 2;
    const int tn = (tid & 15) << 2;
    const float* Ab = g_h1 + (size_t)t * (HH * BB);
    unsigned long long accL[4] = {}, accH[4] = {};
    for (int k0 = 0; k0 < HH; k0 += 16) {
        {
            int b = tid & 63, kk = tid >> 6;
#pragma unroll
            for (int s = 0; s < 4; s++) {
                int k = kk * 4 + s;
                float v = Ab[(size_t)(k0 + k) * BB + b];
                As[k][b] = v * g_scale[k0 + k] + g_shift[k0 + k];
            }
        }
        {
            int k = tid >> 4, c = (tid & 15) << 2;
            float4 v = *reinterpret_cast<const float4*>(W + (size_t)(k0 + k) * G4 + n0 + c);
            Bs[k][c] = v.x; Bs[k][c + 1] = v.y; Bs[k][c + 2] = v.z; Bs[k][c + 3] = v.w;
        }
        __syncthreads();
#pragma unroll
        for (int k = 0; k < 16; k++) {
            float4 a = *reinterpret_cast<const float4*>(&As[k][tm]);
            ulonglong2 bv = *reinterpret_cast<const ulonglong2*>(&Bs[k][tn]);
            unsigned long long a0 = pack2(a.x, a.x), a1 = pack2(a.y, a.y);
            unsigned long long a2 = pack2(a.z, a.z), a3 = pack2(a.w, a.w);
            accL[0] = ffma2(a0, bv.x, accL[0]); accH[0] = ffma2(a0, bv.y, accH[0]);
            accL[1] = ffma2(a1, bv.x, accL[1]); accH[1] = ffma2(a1, bv.y, accH[1]);
            accL[2] = ffma2(a2, bv.x, accL[2]); accH[2] = ffma2(a2, bv.y, accH[2]);
            accL[3] = ffma2(a3, bv.x, accL[3]); accH[3] = ffma2(a3, bv.y, accH[3]);
        }
        __syncthreads();
    }
    float4 bvb = *reinterpret_cast<const float4*>(bias + n0 + tn);
#pragma unroll
    for (int i = 0; i < 4; i++) {
        int orow = t * 64 + tm + i;
        float2 lo = unpack2(accL[i]), hi = unpack2(accH[i]);
        float4 o;
        o.x = lo.x + bvb.x; o.y = lo.y + bvb.y;
        o.z = hi.x + bvb.z; o.w = hi.y + bvb.w;
        *reinterpret_cast<float4*>(g_xw + (size_t)orow * G4 + n0 + tn) = o;
    }
}

// ---------------- persistent LSTM layer (R12 + per-slice mbarrier gating) ---------
// 128 blocks (32 clusters x 4 CTAs) x 512 threads. Block owns 4 units = 16 z-cols
// x 64 batches. Fill: CTA rank r multicasts slice r (rows 64r..64r+63) and slice
// 4+r (rows 256+64r..+63), each 16 KB, to all 4 CTAs. EIGHT mbarriers, one per
// slice (expect_tx = 16384). Warp wk waits only on slice wk>>1 (A-part) and
// slice 4+(wk>>1) (B-part) -> gating = one slice instead of max-of-four.
// smem: [w2 32KB][h_s 128KB][part 32KB][zb 4.25KB][8 mbar 64B] = 201,024 B
#define SMEM_LSTM (32768 + 131072 + 32768 + 16 * 68 * 4 + 64)
__global__ __launch_bounds__(512) void lstm_layer(const float* __restrict__ Wh, int layer) {
    extern __shared__ __align__(16) char smem[];
    float2* w2  = reinterpret_cast<float2*>(smem);                 // [512][8] col-pairs
    float*  h_s = reinterpret_cast<float*>(smem + 32768);          // [512][64]
    float*  part = reinterpret_cast<float*>(smem + 163840);        // [8][8][64] f32x2
    float*  zb  = reinterpret_cast<float*>(smem + 196608);         // [16][68]
    const unsigned smem_base = (unsigned)__cvta_generic_to_shared(smem);
    const unsigned hsa  = smem_base + 32768;
    const unsigned mb0  = smem_base + 200960;     // 8 mbarriers, 8 B each

    const int tid = threadIdx.x;
    const int lane = tid & 31;
    const int w = tid >> 5;                 // warp 0..15
    const int wj = w & 1, wk = w >> 1;
    const int u0 = blockIdx.x << 2;
    float* hseq = layer ? g_h2 : g_h1;
    unsigned* bar = &g_bar[layer];

    unsigned int rank;
    asm("mov.u32 %0, %%cluster_ctarank;" : "=r"(rank));
    const unsigned sliceA_off = rank * 16384u;            // slice rank   (chunk A)
    const unsigned sliceB_off = 65536u + rank * 16384u;   // slice 4+rank (chunk B)

    // this warp's gating barriers
    const unsigned mybarA = mb0 + ((unsigned)(wk >> 1)) * 8u;
    const unsigned mybarB = mb0 + (4u + (unsigned)(wk >> 1)) * 8u;

    // epilogue mapping (tid < 256)
    const int u2 = (tid >> 6) & 3, b_e = tid & 63;
    const size_t sidx = (size_t)(u0 + u2) * BB + b_e;
    float c_reg = 0.f;

    // reducer mapping: thread -> (jpg: col-pair 0..7, br: batch 0..63)
    const int jpg = tid >> 6;
    const int br = tid & 63;
    const int xcol = ((jpg >> 1) * HH) + u0 + ((jpg & 1) * 2);  // col of j=2*jpg

    // mbarriers (count = 1: the local expect_tx arrival per slice)
    if (tid == 0) {
#pragma unroll
        for (int q = 0; q < 8; q++) {
            asm volatile("mbarrier.init.shared.b64 [%0], 1;"
                         :: "r"(mb0 + q * 8u) : "memory");
        }
    }

    // one-time: Wh slice as natural f32x2 col-pairs: w2[k][jp] = (Wh[k][c], Wh[k][c+1])
    for (int idx = tid; idx < 512 * 8; idx += 512) {
        int k = idx >> 3, jp = idx & 7;
        int col = ((jp >> 1) * HH) + u0 + ((jp & 1) * 2);
        const float* p = Wh + (size_t)k * G4 + col;
        w2[idx] = make_float2(__ldg(p), __ldg(p + 1));
    }
    __syncthreads();   // mbarrier init + w2 visible within CTA

    // cluster sync: peers' mbarriers must be live before any multicast lands
    asm volatile("barrier.cluster.arrive.aligned;" ::: "memory");
    asm volatile("barrier.cluster.wait.aligned;" ::: "memory");

    // prefetch xw for t=0
    unsigned long long nxw;
    {
        float2 v = __ldg(reinterpret_cast<const float2*>(g_xw + (size_t)br * G4 + xcol));
        nxw = pack2(v.x, v.y);
    }

    for (int t = 0; t < TT; t++) {
        const float* hin = g_hT[t & 1];
        float* hout = g_hT[(t & 1) ^ 1];
        const unsigned parity = (unsigned)(t & 1);
        const char* hinb = reinterpret_cast<const char*>(hin);

        // per-slice expect_tx (local) + this CTA's two multicast slices
        if (tid == 0) {
#pragma unroll
            for (int q = 0; q < 8; q++) {
                asm volatile("mbarrier.arrive.expect_tx.shared.b64 _, [%0], %1;"
                             :: "r"(mb0 + q * 8u), "r"(16384u) : "memory");
            }
            asm volatile(
                "cp.async.bulk.shared::cluster.global.mbarrier::complete_tx::bytes"
                ".multicast::cluster [%0], [%1], %2, [%3], %4;"
                :: "r"(hsa + sliceA_off), "l"(hinb + sliceA_off),
                   "r"(16384u), "r"(mb0 + rank * 8u), "h"((unsigned short)0xF) : "memory");
            asm volatile(
                "cp.async.bulk.shared::cluster.global.mbarrier::complete_tx::bytes"
                ".multicast::cluster [%0], [%1], %2, [%3], %4;"
                :: "r"(hsa + sliceB_off), "l"(hinb + sliceB_off),
                   "r"(16384u), "r"(mb0 + (4u + rank) * 8u), "h"((unsigned short)0xF) : "memory");
        }

        unsigned long long curxw = nxw;
        if (t + 1 < TT) {
            float2 v = __ldg(reinterpret_cast<const float2*>(
                g_xw + (size_t)(t + 1) * (BB * G4) + (size_t)br * G4 + xcol));
            nxw = pack2(v.x, v.y);
        }

        unsigned long long acc0 = 0, acc1 = 0, acc2 = 0, acc3 = 0;
        unsigned long long acc4 = 0, acc5 = 0, acc6 = 0, acc7 = 0;

#define COMPUTE_KS(kbase)                                                        \
        _Pragma("unroll 8")                                                      \
        for (int kk = 0; kk < 32; kk++) {                                        \
            int k = (kbase) + kk;                                               \
            float2 h2 = *reinterpret_cast<const float2*>(h_s + k * 64 + (lane << 1)); \
            unsigned long long hd0 = pack2(h2.x, h2.x);                          \
            unsigned long long hd1 = pack2(h2.y, h2.y);                          \
            const ulonglong2* wp = reinterpret_cast<const ulonglong2*>(w2 + k * 8 + (wj << 2)); \
            ulonglong2 wva = wp[0];                                              \
            ulonglong2 wvb = wp[1];                                              \
            acc0 = ffma2(wva.x, hd0, acc0); acc1 = ffma2(wva.x, hd1, acc1);      \
            acc2 = ffma2(wva.y, hd0, acc2); acc3 = ffma2(wva.y, hd1, acc3);      \
            acc4 = ffma2(wvb.x, hd0, acc4); acc5 = ffma2(wvb.x, hd1, acc5);      \
            acc6 = ffma2(wvb.y, hd0, acc6); acc7 = ffma2(wvb.y, hd1, acc7);      \
        }

        mbar_wait(mybarA, parity);                 // this warp's A-slice landed
        COMPUTE_KS(wk * 32)                        // A-part: k in [32wk, 32wk+32)

        mbar_wait(mybarB, parity);                 // this warp's B-slice landed
        COMPUTE_KS(256 + wk * 32)                  // B-part

        // write k-partials: part[wk][jp][b] f32x2; wk stride = 1024 floats (4 KB)
        {
            float* pb = part + wk * 1024 + (wj << 2) * 128 + (lane << 2);
            ulonglong2 v0; v0.x = acc0; v0.y = acc1;
            ulonglong2 v1; v1.x = acc2; v1.y = acc3;
            ulonglong2 v2; v2.x = acc4; v2.y = acc5;
            ulonglong2 v3; v3.x = acc6; v3.y = acc7;
            *reinterpret_cast<ulonglong2*>(pb)       = v0;
            *reinterpret_cast<ulonglong2*>(pb + 128) = v1;
            *reinterpret_cast<ulonglong2*>(pb + 256) = v2;
            *reinterpret_cast<ulonglong2*>(pb + 384) = v3;
        }
        __syncthreads();

        // reduce over 8 k-slices, deterministic: z = xw + sum_{wk=0..7} part
        {
            unsigned long long s = curxw;
            const float* pr = part + jpg * 128 + (br << 1);
#pragma unroll
            for (int q = 0; q < 8; q++) {
                unsigned long long p = *reinterpret_cast<const unsigned long long*>(pr + q * 1024);
                s = addf2(s, p);
            }
            float2 sf = unpack2(s);
            zb[(jpg << 1) * 68 + br]       = sf.x;
            zb[((jpg << 1) + 1) * 68 + br] = sf.y;
        }
        __syncthreads();

        // gates + state update (256 threads: 4 units x 64 batches)
        if (tid < 256) {
            float zi = zb[u2 * 68 + b_e],        zf = zb[(4 + u2) * 68 + b_e];
            float zg = zb[(8 + u2) * 68 + b_e],  zo = zb[(12 + u2) * 68 + b_e];
            float ig = 1.f / (1.f + expf(-zi));
            float fg = 1.f / (1.f + expf(-zf));
            float og = 1.f / (1.f + expf(-zo));
            float gg = tanhf(zg);
            c_reg = fg * c_reg + ig * gg;
            float hn = og * tanhf(c_reg);
            hout[sidx] = hn;
            hseq[(size_t)t * (HH * BB) + sidx] = hn;
        }
        // grid barrier: all blocks finish hout before next step
        __threadfence();
        __syncthreads();
        if (tid == 0) {
            atomicAdd(bar, 1u);
            unsigned target = (unsigned)(t + 1) * 128u;
            while (*(volatile unsigned*)bar < target) { __nanosleep(16); }
        }
        __syncthreads();
#undef COMPUTE_KS
    }

    // cluster sync before exit: no CTA leaves while peers' multicasts could target it
    asm volatile("barrier.cluster.arrive.aligned;" ::: "memory");
    asm volatile("barrier.cluster.wait.aligned;" ::: "memory");
}

// ---------------- BN stats (training mode), folded scale/shift, deterministic -------
__global__ __launch_bounds__(256) void bn_stats(int layer, const float* __restrict__ gamma,
                                                const float* __restrict__ beta) {
    const float* h = layer ? g_h2 : g_h1;
    const int kf = blockIdx.x;
    const int tid = threadIdx.x;
    float s = 0.f, ss = 0.f;
    for (int lin = tid; lin < NR; lin += 256) {
        float v = h[(size_t)(lin >> 6) * (HH * BB) + (size_t)kf * BB + (lin & 63)];
        s += v; ss += v * v;
    }
    __shared__ float rs[256], rq[256];
    rs[tid] = s; rq[tid] = ss;
    __syncthreads();
    for (int off = 128; off > 0; off >>= 1) {
        if (tid < off) { rs[tid] += rs[tid + off]; rq[tid] += rq[tid + off]; }
        __syncthreads();
    }
    if (tid == 0) {
        float mean = rs[0] * (1.f / 32768.f);
        float var = rq[0] * (1.f / 32768.f) - mean * mean;
        float rstd = rsqrtf(var + 1e-5f);
        float sc = rstd * gamma[kf];
        g_scale[layer * HH + kf] = sc;
        g_shift[layer * HH + kf] = beta[kf] - mean * sc;
    }
}

// ---------------- Dense head ----------------
__global__ __launch_bounds__(256) void dense_out(const float* __restrict__ Wd1,
                                                 const float* __restrict__ bd1,
                                                 const float* __restrict__ Wd2,
                                                 const float* __restrict__ bd2,
                                                 float* __restrict__ out) {
    __shared__ float hs[64][68];
    __shared__ float ws[64][16];
    __shared__ float sp[4][64];
    const int t = blockIdx.x, tid = threadIdx.x;
    const int b = tid & 63, jg = tid >> 6;
    float a0 = 0.f, a1 = 0.f, a2 = 0.f, a3 = 0.f;
    for (int k0 = 0; k0 < HH; k0 += 64) {
#pragma unroll
        for (int i = 0; i < 16; i++) {
            int lin = tid + i * 256; int k = lin >> 6, bb = lin & 63;
            float v = g_h2[(size_t)t * (HH * BB) + (size_t)(k0 + k) * BB + bb];
            hs[k][bb] = v * g_scale[HH + k0 + k] + g_shift[HH + k0 + k];
        }
#pragma unroll
        for (int i = 0; i < 4; i++) {
            int lin = tid + i * 256; int jj = lin & 15, k = lin >> 4;
            ws[k][jj] = Wd1[(size_t)(k0 + k) * 16 + jj];
        }
        __syncthreads();
#pragma unroll
        for (int k = 0; k < 64; k++) {
            float hv = hs[k][b];
            a0 += hv * ws[k][jg * 4 + 0];
            a1 += hv * ws[k][jg * 4 + 1];
            a2 += hv * ws[k][jg * 4 + 2];
            a3 += hv * ws[k][jg * 4 + 3];
        }
        __syncthreads();
    }
    float p = fmaxf(a0 + bd1[jg * 4 + 0], 0.f) * Wd2[jg * 4 + 0]
            + fmaxf(a1 + bd1[jg * 4 + 1], 0.f) * Wd2[jg * 4 + 1]
            + fmaxf(a2 + bd1[jg * 4 + 2], 0.f) * Wd2[jg * 4 + 2]
            + fmaxf(a3 + bd1[jg * 4 + 3], 0.f) * Wd2[jg * 4 + 3];
    sp[jg][b] = p;
    __syncthreads();
    if (tid < 64) {
        out[(size_t)tid * TT + t] = sp[0][tid] + sp[1][tid] + sp[2][tid] + sp[3][tid] + bd2[0];
    }
}

// ---------------- launch (9 graph nodes) ----------------
extern "C" void kernel_launch(void* const* d_in, const int* in_sizes, int n_in,
                              void* d_out, int out_size) {
    const float* x   = (const float*)d_in[0];
    const float* Wx1 = (const float*)d_in[1];
    const float* Wh1 = (const float*)d_in[2];
    const float* b1  = (const float*)d_in[3];
    const float* g1  = (const float*)d_in[4];
    const float* be1 = (const float*)d_in[5];
    const float* Wx2 = (const float*)d_in[6];
    const float* Wh2 = (const float*)d_in[7];
    const float* b2  = (const float*)d_in[8];
    const float* g2  = (const float*)d_in[9];
    const float* be2 = (const float*)d_in[10];
    const float* Wd1 = (const float*)d_in[11];
    const float* bd1 = (const float*)d_in[12];
    const float* Wd2 = (const float*)d_in[13];
    const float* bd2 = (const float*)d_in[14];
    float* out = (float*)d_out;

    static bool attr_set = false;
    if (!attr_set) {
        cudaFuncSetAttribute(lstm_layer, cudaFuncAttributeMaxDynamicSharedMemorySize, SMEM_LSTM);
        attr_set = true;
    }

    // cluster launch config for the scans (4-CTA clusters for TMA multicast)
    cudaLaunchConfig_t cfg = {};
    cfg.gridDim = dim3(128, 1, 1);
    cfg.blockDim = dim3(512, 1, 1);
    cfg.dynamicSmemBytes = SMEM_LSTM;
    cfg.stream = 0;
    cudaLaunchAttribute attrs[1];
    attrs[0].id = cudaLaunchAttributeClusterDimension;
    attrs[0].val.clusterDim = {4, 1, 1};
    cfg.attrs = attrs;
    cfg.numAttrs = 1;

    zero_state<<<64, 512>>>();
    gemm_xw1<<<dim3(32, 512), 256>>>(x, Wx1, b1);
    cudaLaunchKernelEx(&cfg, lstm_layer, Wh1, 0);
    bn_stats<<<512, 256>>>(0, g1, be1);
    gemm_xw2<<<dim3(32, 512), 256>>>(Wx2, b2);
    zero_state<<<64, 512>>>();
    cudaLaunchKernelEx(&cfg, lstm_layer, Wh2, 1);
    bn_stats<<<512, 256>>>(1, g2, be2);
    dense_out<<<512, 256>>>(Wd1, bd1, Wd2, bd2, out);
}